// round 15
// baseline (speedup 1.0000x reference)
#include <cuda_runtime.h>
#include <cuda_bf16.h>

#define MAXN 8192
__device__ float4 g_pt[MAXN];   // x, y, ell, theta/tau per point

#define TPB 128
#define ILP 4            // scalar i-lanes per thread
#define JT  32

// One pair interaction, fully scalar, single fused asm block.
// Add/sub-class ops use FFMA with +/-1.0 immediate multiplier -> rt_SMSP=1
// (full-rate fp32 path); only the 5 reg*reg ops pay rt=2.
#define PAIR1(FL, FT, XJ, YJ, LJ, TJ, SJ, XI, YI, LI, TI, EPS, MG, NMG, CUT) \
    asm("{\n\t" \
        ".reg .f32 dx, dy, t0, d2, r, f, dl, u, t1, w, dth;\n\t" \
        ".reg .pred p;\n\t" \
        "fma.rn.f32 dx, %7, 0fBF800000, %2;\n\t"  /* xj - xi   (imm -1) */ \
        "fma.rn.f32 dy, %8, 0fBF800000, %3;\n\t"  /* yj - yi            */ \
        "fma.rn.f32 t0, dy, dy, %11;\n\t"         /* dy^2 + 1e-30       */ \
        "fma.rn.f32 d2, dx, dx, t0;\n\t" \
        "rsqrt.approx.f32 r, d2;\n\t" \
        "setp.gt.f32 p, d2, %14;\n\t"             /* parallel with rsqrt */ \
        "selp.f32 r, 0f00000000, r, p;\n\t" \
        "mul.rn.f32 f, r, %6;\n\t"                /* f = s_j / dist      */ \
        "fma.rn.f32 dl, %9, 0fBF800000, %4;\n\t"  /* lj - li             */ \
        "fma.rn.f32 u,  %10, 0fBF800000, %5;\n\t" /* tn_j - tn_i (-1,1)  */ \
        "fma.rn.f32 t1, u, 0f3F800000, %12;\n\t"  /* u + M  (magic rint) */ \
        "fma.rn.f32 w,  t1, 0f3F800000, %13;\n\t" /* (u+M) - M = rint(u) */ \
        "fma.rn.f32 dth, w, 0fBF800000, u;\n\t"   /* u - rint(u)         */ \
        "fma.rn.f32 %0, f, dl, %0;\n\t" \
        "fma.rn.f32 %1, f, dth, %1;\n\t" \
        "}" \
        : "+f"(FL), "+f"(FT) \
        : "f"(XJ), "f"(YJ), "f"(LJ), "f"(TJ), "f"(SJ), \
          "f"(XI), "f"(YI), "f"(LI), "f"(TI), \
          "f"(EPS), "f"(MG), "f"(NMG), "f"(CUT))

__global__ void precompute_xy(const float* __restrict__ ell,
                              const float* __restrict__ theta,
                              float* __restrict__ out, int N) {
    const float INV_TAU = 0.15915494309189533577f;
    int i = blockIdx.x * blockDim.x + threadIdx.x;
    if (i < N) {
        float e = ell[i];
        float t = theta[i];
        float r = expf(e);
        float sn, cs;
        sincosf(t, &sn, &cs);
        float ax = r * (fabsf(cs) + 1e-10f);
        float ay = r * (fabsf(sn) + 1e-10f);
        float4 p;
        p.x = (cs >= 0.f) ? ax : -ax;
        p.y = (sn >= 0.f) ? ay : -ay;
        p.z = e;
        p.w = t * INV_TAU;                 // normalized theta (turns)
        g_pt[i] = p;
        out[i]     = 0.f;                  // fused output zeroing
        out[N + i] = 0.f;
    }
}

__global__ void __launch_bounds__(TPB)
force_kernel(const float* __restrict__ s, const unsigned char* __restrict__ frozen,
             float* __restrict__ out, int N)
{
    __shared__ float4 sj4[JT];             // x, y, ell, tn
    __shared__ float  sS[JT];

    const float CUT2  = 6.854101966249685f;      // phi^4
    const float TAU_F = 6.28318530717958647692f;
    const float EPSC  = 1e-30f;                  // diagonal: finite r, dl==dth==0
    const float MAGC  = 12582912.0f;             // 1.5*2^23
    const float NMAGC = -12582912.0f;

    int tid = threadIdx.x;
    int ibase = blockIdx.x * (TPB * ILP) + tid;

    // ---- prefetch i-data first (overlap LDG latency with j-tile fill) ----
    float4 qi[ILP];
#pragma unroll
    for (int k = 0; k < ILP; k++) {
        int i = ibase + k * TPB;
        qi[k] = (i < N) ? g_pt[i] : make_float4(1e30f, 1e30f, 0.f, 0.f);
    }

    // ---- j tile ----
    if (tid < JT) {
        int j = blockIdx.y * JT + tid;
        if (j < N) {
            sj4[tid] = g_pt[j];
            sS[tid]  = s[j];
        } else {
            sj4[tid] = make_float4(-1e30f, -1e30f, 0.f, 0.f);  // fails cutoff
            sS[tid]  = 0.f;
        }
    }

    float fl[ILP], ft[ILP];
#pragma unroll
    for (int k = 0; k < ILP; k++) { fl[k] = 0.f; ft[k] = 0.f; }

    __syncthreads();

#pragma unroll 4
    for (int jj = 0; jj < JT; jj++) {
        float4 J = sj4[jj];                // LDS.128
        float  Sj = sS[jj];                // LDS.32
#pragma unroll
        for (int k = 0; k < ILP; k++) {
            PAIR1(fl[k], ft[k], J.x, J.y, J.z, J.w, Sj,
                  qi[k].x, qi[k].y, qi[k].z, qi[k].w,
                  EPSC, MAGC, NMAGC, CUT2);
        }
    }

#pragma unroll
    for (int k = 0; k < ILP; k++) {
        int i = ibase + k * TPB;
        if (i < N) {
            float m = frozen[i] ? 0.f : s[i];
            atomicAdd(&out[i],     m * fl[k]);
            atomicAdd(&out[N + i], (m * TAU_F) * ft[k]);   // turns -> radians
        }
    }
}

extern "C" void kernel_launch(void* const* d_in, const int* in_sizes, int n_in,
                              void* d_out, int out_size) {
    const float*         ell    = (const float*)d_in[0];
    const float*         theta  = (const float*)d_in[1];
    const float*         s      = (const float*)d_in[2];
    const unsigned char* frozen = (const unsigned char*)d_in[3];
    float* out = (float*)d_out;
    int N = in_sizes[0];

    precompute_xy<<<(N + 255) / 256, 256>>>(ell, theta, out, N);

    dim3 grid((N + TPB * ILP - 1) / (TPB * ILP), (N + JT - 1) / JT);
    force_kernel<<<grid, TPB>>>(s, frozen, out, N);
}

// round 16
// speedup vs baseline: 1.0326x; 1.0326x over previous
#include <cuda_runtime.h>
#include <cuda_bf16.h>

#define MAXN 8192
__device__ float4 g_pt[MAXN];   // x, y, ell, theta/tau per point

#define TPB 128
#define ILP 4            // scalar i-lanes per thread, 2 per fused asm block
#define JT  32

// Two pair interactions, manually interleaved in ONE asm block:
// guaranteed 2-way ILP at SASS level; RSQ latency covered by 12 intervening ops.
// Add/sub ops use FFMA with +/-1.0 immediate (full-rate imm form).
// Cutoff via predicate on the accumulating FFMAs (no SELP).
#define PAIR2(FL0, FT0, FL1, FT1, JX, JY, JL, JTH, SJ, \
              X0, Y0, L0, T0, X1, Y1, L1, T1, EPS, MG, NMG, CUT) \
    asm("{\n\t" \
        ".reg .f32 dx0,dy0,t00,d20,r0,f0,dl0,u0,t10,w0,dth0;\n\t" \
        ".reg .f32 dx1,dy1,t01,d21,r1,f1,dl1,u1,t11,w1,dth1;\n\t" \
        ".reg .pred p0,p1;\n\t" \
        "fma.rn.f32 dx0, %9,  0fBF800000, %4;\n\t"   /* xj - xi0 */ \
        "fma.rn.f32 dx1, %13, 0fBF800000, %4;\n\t" \
        "fma.rn.f32 dy0, %10, 0fBF800000, %5;\n\t" \
        "fma.rn.f32 dy1, %14, 0fBF800000, %5;\n\t" \
        "fma.rn.f32 t00, dy0, dy0, %17;\n\t"         /* +1e-30: diag finite */ \
        "fma.rn.f32 t01, dy1, dy1, %17;\n\t" \
        "fma.rn.f32 d20, dx0, dx0, t00;\n\t" \
        "fma.rn.f32 d21, dx1, dx1, t01;\n\t" \
        "rsqrt.approx.f32 r0, d20;\n\t" \
        "rsqrt.approx.f32 r1, d21;\n\t" \
        "setp.le.f32 p0, d20, %20;\n\t" \
        "setp.le.f32 p1, d21, %20;\n\t" \
        "fma.rn.f32 dl0, %11, 0fBF800000, %6;\n\t"   /* lj - li */ \
        "fma.rn.f32 dl1, %15, 0fBF800000, %6;\n\t" \
        "fma.rn.f32 u0,  %12, 0fBF800000, %7;\n\t"   /* tn_j - tn_i */ \
        "fma.rn.f32 u1,  %16, 0fBF800000, %7;\n\t" \
        "fma.rn.f32 t10, u0, 0f3F800000, %18;\n\t"   /* u + M (magic rint) */ \
        "fma.rn.f32 t11, u1, 0f3F800000, %18;\n\t" \
        "fma.rn.f32 w0,  t10, 0f3F800000, %19;\n\t"  /* rint(u) */ \
        "fma.rn.f32 w1,  t11, 0f3F800000, %19;\n\t" \
        "fma.rn.f32 dth0, w0, 0fBF800000, u0;\n\t"   /* u - rint(u) */ \
        "fma.rn.f32 dth1, w1, 0fBF800000, u1;\n\t" \
        "mul.rn.f32 f0, r0, %8;\n\t"                 /* s_j / dist */ \
        "mul.rn.f32 f1, r1, %8;\n\t" \
        "@p0 fma.rn.f32 %0, f0, dl0,  %0;\n\t" \
        "@p1 fma.rn.f32 %2, f1, dl1,  %2;\n\t" \
        "@p0 fma.rn.f32 %1, f0, dth0, %1;\n\t" \
        "@p1 fma.rn.f32 %3, f1, dth1, %3;\n\t" \
        "}" \
        : "+f"(FL0), "+f"(FT0), "+f"(FL1), "+f"(FT1) \
        : "f"(JX), "f"(JY), "f"(JL), "f"(JTH), "f"(SJ), \
          "f"(X0), "f"(Y0), "f"(L0), "f"(T0), \
          "f"(X1), "f"(Y1), "f"(L1), "f"(T1), \
          "f"(EPS), "f"(MG), "f"(NMG), "f"(CUT))

__global__ void precompute_xy(const float* __restrict__ ell,
                              const float* __restrict__ theta,
                              float* __restrict__ out, int N) {
    const float INV_TAU = 0.15915494309189533577f;
    int i = blockIdx.x * blockDim.x + threadIdx.x;
    if (i < N) {
        float e = ell[i];
        float t = theta[i];
        float r = expf(e);
        float sn, cs;
        sincosf(t, &sn, &cs);
        float ax = r * (fabsf(cs) + 1e-10f);
        float ay = r * (fabsf(sn) + 1e-10f);
        float4 p;
        p.x = (cs >= 0.f) ? ax : -ax;
        p.y = (sn >= 0.f) ? ay : -ay;
        p.z = e;
        p.w = t * INV_TAU;                 // normalized theta (turns)
        g_pt[i] = p;
        out[i]     = 0.f;                  // fused output zeroing
        out[N + i] = 0.f;
    }
}

__global__ void __launch_bounds__(TPB, 7)   // <=73 regs: all 1024 CTAs resident, one wave
force_kernel(const float* __restrict__ s, const unsigned char* __restrict__ frozen,
             float* __restrict__ out, int N)
{
    __shared__ float4 sj4[JT];             // x, y, ell, tn
    __shared__ float  sS[JT];

    const float CUT2  = 6.854101966249685f;      // phi^4
    const float TAU_F = 6.28318530717958647692f;
    const float EPSC  = 1e-30f;                  // diagonal: finite r, dl==dth==0
    const float MAGC  = 12582912.0f;             // 1.5*2^23
    const float NMAGC = -12582912.0f;

    int tid = threadIdx.x;
    int ibase = blockIdx.x * (TPB * ILP) + tid;

    // ---- prefetch i-data first (overlap LDG latency with j-tile fill) ----
    float4 qi[ILP];
#pragma unroll
    for (int k = 0; k < ILP; k++) {
        int i = ibase + k * TPB;
        qi[k] = (i < N) ? g_pt[i] : make_float4(1e30f, 1e30f, 0.f, 0.f);
    }

    // ---- j tile ----
    if (tid < JT) {
        int j = blockIdx.y * JT + tid;
        if (j < N) {
            sj4[tid] = g_pt[j];
            sS[tid]  = s[j];
        } else {
            sj4[tid] = make_float4(-1e30f, -1e30f, 0.f, 0.f);  // fails cutoff
            sS[tid]  = 0.f;
        }
    }

    float fl[ILP], ft[ILP];
#pragma unroll
    for (int k = 0; k < ILP; k++) { fl[k] = 0.f; ft[k] = 0.f; }

    __syncthreads();

#pragma unroll 4
    for (int jj = 0; jj < JT; jj++) {
        float4 J = sj4[jj];                // LDS.128
        float  Sj = sS[jj];                // LDS.32
        PAIR2(fl[0], ft[0], fl[1], ft[1], J.x, J.y, J.z, J.w, Sj,
              qi[0].x, qi[0].y, qi[0].z, qi[0].w,
              qi[1].x, qi[1].y, qi[1].z, qi[1].w,
              EPSC, MAGC, NMAGC, CUT2);
        PAIR2(fl[2], ft[2], fl[3], ft[3], J.x, J.y, J.z, J.w, Sj,
              qi[2].x, qi[2].y, qi[2].z, qi[2].w,
              qi[3].x, qi[3].y, qi[3].z, qi[3].w,
              EPSC, MAGC, NMAGC, CUT2);
    }

#pragma unroll
    for (int k = 0; k < ILP; k++) {
        int i = ibase + k * TPB;
        if (i < N) {
            float m = frozen[i] ? 0.f : s[i];
            atomicAdd(&out[i],     m * fl[k]);
            atomicAdd(&out[N + i], (m * TAU_F) * ft[k]);   // turns -> radians
        }
    }
}

extern "C" void kernel_launch(void* const* d_in, const int* in_sizes, int n_in,
                              void* d_out, int out_size) {
    const float*         ell    = (const float*)d_in[0];
    const float*         theta  = (const float*)d_in[1];
    const float*         s      = (const float*)d_in[2];
    const unsigned char* frozen = (const unsigned char*)d_in[3];
    float* out = (float*)d_out;
    int N = in_sizes[0];

    precompute_xy<<<(N + 255) / 256, 256>>>(ell, theta, out, N);

    dim3 grid((N + TPB * ILP - 1) / (TPB * ILP), (N + JT - 1) / JT);
    force_kernel<<<grid, TPB>>>(s, frozen, out, N);
}

// round 17
// speedup vs baseline: 1.0732x; 1.0393x over previous
#include <cuda_runtime.h>
#include <cuda_bf16.h>

#define MAXN 8192
__device__ float4 g_pt[MAXN];   // x, y, ell, theta-as-u32-turn (bit-cast)

#define TPB 128
#define ILP 4            // scalar i-lanes per thread, 2 per fused asm block
#define JT  32

// Two pair interactions interleaved in ONE asm block.
// Angle wrap done on the ALU pipe: dt = (s32)(tj_u32 - ti_u32) is the exact
// wrapped delta in 2^-32-turn units (integer overflow == mod tau). The fma
// pipe carries only 8 ops/pair: dx, dy, t0, d2, dl, f, 2 accums.
#define PAIR2(FL0, FT0, FL1, FT1, JX, JY, JL, JTI, SJ, \
              X0, Y0, L0, TI0, X1, Y1, L1, TI1, EPS, CUT) \
    asm("{\n\t" \
        ".reg .f32 dx0,dy0,t00,d20,r0,f0,dl0,dth0;\n\t" \
        ".reg .f32 dx1,dy1,t01,d21,r1,f1,dl1,dth1;\n\t" \
        ".reg .s32 dt0,dt1;\n\t" \
        ".reg .pred p0,p1;\n\t" \
        "fma.rn.f32 dx0, %9,  0fBF800000, %4;\n\t"   /* xj - xi0 (imm -1) */ \
        "fma.rn.f32 dx1, %13, 0fBF800000, %4;\n\t" \
        "fma.rn.f32 dy0, %10, 0fBF800000, %5;\n\t" \
        "fma.rn.f32 dy1, %14, 0fBF800000, %5;\n\t" \
        "fma.rn.f32 t00, dy0, dy0, %17;\n\t"         /* +1e-30: diag finite */ \
        "fma.rn.f32 t01, dy1, dy1, %17;\n\t" \
        "fma.rn.f32 d20, dx0, dx0, t00;\n\t" \
        "fma.rn.f32 d21, dx1, dx1, t01;\n\t" \
        "rsqrt.approx.f32 r0, d20;\n\t" \
        "rsqrt.approx.f32 r1, d21;\n\t" \
        "setp.le.f32 p0, d20, %18;\n\t" \
        "setp.le.f32 p1, d21, %18;\n\t" \
        "sub.s32 dt0, %8, %12;\n\t"                  /* wrapped: mod 2^32 */ \
        "sub.s32 dt1, %8, %16;\n\t" \
        "cvt.rn.f32.s32 dth0, dt0;\n\t"              /* [-0.5,0.5) turns *2^32 */ \
        "cvt.rn.f32.s32 dth1, dt1;\n\t" \
        "fma.rn.f32 dl0, %11, 0fBF800000, %6;\n\t"   /* lj - li */ \
        "fma.rn.f32 dl1, %15, 0fBF800000, %6;\n\t" \
        "mul.rn.f32 f0, r0, %7;\n\t"                 /* s_j / dist */ \
        "mul.rn.f32 f1, r1, %7;\n\t" \
        "@p0 fma.rn.f32 %0, f0, dl0,  %0;\n\t" \
        "@p1 fma.rn.f32 %2, f1, dl1,  %2;\n\t" \
        "@p0 fma.rn.f32 %1, f0, dth0, %1;\n\t" \
        "@p1 fma.rn.f32 %3, f1, dth1, %3;\n\t" \
        "}" \
        : "+f"(FL0), "+f"(FT0), "+f"(FL1), "+f"(FT1) \
        : "f"(JX), "f"(JY), "f"(JL), "f"(SJ), "r"(JTI), \
          "f"(X0), "f"(Y0), "f"(L0), "r"(TI0), \
          "f"(X1), "f"(Y1), "f"(L1), "r"(TI1), \
          "f"(EPS), "f"(CUT))

__global__ void precompute_xy(const float* __restrict__ ell,
                              const float* __restrict__ theta,
                              float* __restrict__ out, int N) {
    int i = blockIdx.x * blockDim.x + threadIdx.x;
    if (i < N) {
        float e = ell[i];
        float t = theta[i];
        float r = expf(e);
        float sn, cs;
        sincosf(t, &sn, &cs);
        float ax = r * (fabsf(cs) + 1e-10f);
        float ay = r * (fabsf(sn) + 1e-10f);
        // theta -> u32 fixed-point turns (wraps mod tau by construction)
        double scale = 4294967296.0 / 6.283185307179586476925286766559;
        unsigned ti = (unsigned)(unsigned long long)((double)t * scale);
        float4 p;
        p.x = (cs >= 0.f) ? ax : -ax;
        p.y = (sn >= 0.f) ? ay : -ay;
        p.z = e;
        p.w = __uint_as_float(ti);
        g_pt[i] = p;
        out[i]     = 0.f;                  // fused output zeroing
        out[N + i] = 0.f;
    }
}

__global__ void __launch_bounds__(TPB, 7)
force_kernel(const float* __restrict__ s, const unsigned char* __restrict__ frozen,
             float* __restrict__ out, int N)
{
    __shared__ float4 sj4[JT];             // x, y, ell, ti-bits
    __shared__ float  sS[JT];

    const float CUT2   = 6.854101966249685f;       // phi^4
    const float EPSC   = 1e-30f;
    const float SCL_T  = 1.4629180792671596e-9f;   // tau * 2^-32 (int-turns -> rad)

    int tid = threadIdx.x;
    int ibase = blockIdx.x * (TPB * ILP) + tid;

    // ---- prefetch i-data first (overlap LDG latency with j-tile fill) ----
    float4 qi[ILP];
#pragma unroll
    for (int k = 0; k < ILP; k++) {
        int i = ibase + k * TPB;
        qi[k] = (i < N) ? g_pt[i] : make_float4(1e30f, 1e30f, 0.f, 0.f);
    }

    // ---- j tile ----
    if (tid < JT) {
        int j = blockIdx.y * JT + tid;
        if (j < N) {
            sj4[tid] = g_pt[j];
            sS[tid]  = s[j];
        } else {
            sj4[tid] = make_float4(-1e30f, -1e30f, 0.f, 0.f);  // fails cutoff
            sS[tid]  = 0.f;
        }
    }

    float fl[ILP], ft[ILP];
    int   ti[ILP];
#pragma unroll
    for (int k = 0; k < ILP; k++) {
        fl[k] = 0.f; ft[k] = 0.f;
        ti[k] = (int)__float_as_uint(qi[k].w);
    }

    __syncthreads();

#pragma unroll 4
    for (int jj = 0; jj < JT; jj++) {
        float4 J = sj4[jj];                // LDS.128
        float  Sj = sS[jj];                // LDS.32
        int    Jti = (int)__float_as_uint(J.w);
        PAIR2(fl[0], ft[0], fl[1], ft[1], J.x, J.y, J.z, Jti, Sj,
              qi[0].x, qi[0].y, qi[0].z, ti[0],
              qi[1].x, qi[1].y, qi[1].z, ti[1],
              EPSC, CUT2);
        PAIR2(fl[2], ft[2], fl[3], ft[3], J.x, J.y, J.z, Jti, Sj,
              qi[2].x, qi[2].y, qi[2].z, ti[2],
              qi[3].x, qi[3].y, qi[3].z, ti[3],
              EPSC, CUT2);
    }

#pragma unroll
    for (int k = 0; k < ILP; k++) {
        int i = ibase + k * TPB;
        if (i < N) {
            float m = frozen[i] ? 0.f : s[i];
            atomicAdd(&out[i],     m * fl[k]);
            atomicAdd(&out[N + i], (m * SCL_T) * ft[k]);   // int-turns -> radians
        }
    }
}

extern "C" void kernel_launch(void* const* d_in, const int* in_sizes, int n_in,
                              void* d_out, int out_size) {
    const float*         ell    = (const float*)d_in[0];
    const float*         theta  = (const float*)d_in[1];
    const float*         s      = (const float*)d_in[2];
    const unsigned char* frozen = (const unsigned char*)d_in[3];
    float* out = (float*)d_out;
    int N = in_sizes[0];

    precompute_xy<<<(N + 255) / 256, 256>>>(ell, theta, out, N);

    dim3 grid((N + TPB * ILP - 1) / (TPB * ILP), (N + JT - 1) / JT);
    force_kernel<<<grid, TPB>>>(s, frozen, out, N);
}